// round 2
// baseline (speedup 1.0000x reference)
#include <cuda_runtime.h>
#include <math.h>

#define TOKENS 65536
#define DDIM   512
#define NEXP   8
#define HDIM   2048
#define CAP    65536          // per-expert worst-case token capacity

// ---------------- scratch (no allocs allowed -> __device__ globals) ----------
__device__ int   g_counts [NEXP];
__device__ int   g_offsets[NEXP];
__device__ int   g_tokens [NEXP * CAP];
__device__ float g_gates  [NEXP * CAP];
// compacted hidden activations: 2*TOKENS rows x HDIM  (= 1 GiB)
__device__ float g_hbuf[(size_t)2 * TOKENS * HDIM];

// ---------------- small utility kernels -------------------------------------
__global__ void zero_counts_kernel() {
    if (threadIdx.x < NEXP) g_counts[threadIdx.x] = 0;
}

__global__ void offsets_kernel() {
    if (threadIdx.x == 0) {
        int s = 0;
        #pragma unroll
        for (int e = 0; e < NEXP; e++) { g_offsets[e] = s; s += g_counts[e]; }
    }
}

// ---------------- router: logits -> top2 -> renorm softmax -> gather lists ---
__global__ void router_kernel(const float* __restrict__ x,
                              const float* __restrict__ rw,
                              const float* __restrict__ rb) {
    __shared__ float srw[DDIM * NEXP];           // 16 KB
    int tid = threadIdx.x;
    for (int i = tid; i < DDIM * NEXP; i += blockDim.x) srw[i] = rw[i];
    __syncthreads();

    int warp = tid >> 5, lane = tid & 31;
    int t = blockIdx.x * 8 + warp;               // 8 warps/block, warp per token
    const float* xr = x + (size_t)t * DDIM;

    float acc[NEXP];
    #pragma unroll
    for (int e = 0; e < NEXP; e++) acc[e] = 0.f;
    for (int d = lane; d < DDIM; d += 32) {
        float xv = xr[d];
        #pragma unroll
        for (int e = 0; e < NEXP; e++) acc[e] += xv * srw[d * NEXP + e];
    }
    #pragma unroll
    for (int e = 0; e < NEXP; e++) {
        #pragma unroll
        for (int o = 16; o > 0; o >>= 1)
            acc[e] += __shfl_xor_sync(0xffffffffu, acc[e], o);
    }

    if (lane == 0) {
        float l[NEXP];
        #pragma unroll
        for (int e = 0; e < NEXP; e++) l[e] = acc[e] + rb[e];
        // top-1 (first occurrence on tie, matching lax.top_k)
        int e1 = 0;
        #pragma unroll
        for (int e = 1; e < NEXP; e++) if (l[e] > l[e1]) e1 = e;
        // top-2 excluding e1
        int e2 = (e1 == 0) ? 1 : 0;
        #pragma unroll
        for (int e = 0; e < NEXP; e++)
            if (e != e1 && l[e] > l[e2]) e2 = e;
        // renormalized top-2 softmax weights
        float d2 = expf(l[e2] - l[e1]);
        float g2 = d2 / (1.f + d2);
        float g1 = 1.f - g2;

        int p1 = atomicAdd(&g_counts[e1], 1);
        g_tokens[e1 * CAP + p1] = t;  g_gates[e1 * CAP + p1] = g1;
        int p2 = atomicAdd(&g_counts[e2], 1);
        g_tokens[e2 * CAP + p2] = t;  g_gates[e2 * CAP + p2] = g2;
    }
}

// ---------------- SGEMM tiles -------------------------------------------------
#define BM  128
#define BN  128
#define BKK 16
#define AP  132   // smem pitch (floats), 16B-aligned, bank-stagger
#define BP  132

// GEMM1: h = relu( gather(x) @ w1[e] + b1[e] )   M=count[e], N=2048, K=512
__global__ __launch_bounds__(256, 2)
void gemm1_kernel(const float* __restrict__ x,
                  const float* __restrict__ w1,
                  const float* __restrict__ b1) {
    int e   = blockIdx.z;
    int cnt = g_counts[e];
    int m0  = blockIdx.y * BM;
    if (m0 >= cnt) return;
    int n0  = blockIdx.x * BN;
    int off = g_offsets[e];
    const float* Bw = w1 + (size_t)e * DDIM * HDIM;

    __shared__ float As[BKK * AP];
    __shared__ float Bs[BKK * BP];

    int tid = threadIdx.x;
    // A-load mapping: 2 float4 rows per thread (rows tid/4 and tid/4+64)
    int arow0 = tid >> 2;
    int arow1 = arow0 + 64;
    int acg   = (tid & 3) * 4;  // k-offset within BK tile
    int mr0 = m0 + arow0; if (mr0 > cnt - 1) mr0 = cnt - 1;
    int mr1 = m0 + arow1; if (mr1 > cnt - 1) mr1 = cnt - 1;
    const float* a0p = x + (size_t)g_tokens[e * CAP + mr0] * DDIM + acg;
    const float* a1p = x + (size_t)g_tokens[e * CAP + mr1] * DDIM + acg;

    // B-load mapping: rows tid/32 and tid/32+8, one float4 each
    int brow = tid >> 5;
    int bc   = (tid & 31) * 4;
    const float* b0p = Bw + (size_t)brow * HDIM + n0 + bc;
    const float* b1p = b0p + (size_t)8 * HDIM;

    int tx = tid & 15, ty = tid >> 4;
    float c[8][8];
    #pragma unroll
    for (int i = 0; i < 8; i++)
        #pragma unroll
        for (int j = 0; j < 8; j++) c[i][j] = 0.f;

    for (int k0 = 0; k0 < DDIM; k0 += BKK) {
        float4 av0 = *(const float4*)(a0p + k0);
        float4 av1 = *(const float4*)(a1p + k0);
        float4 bv0 = *(const float4*)(b0p + (size_t)k0 * HDIM);
        float4 bv1 = *(const float4*)(b1p + (size_t)k0 * HDIM);
        __syncthreads();
        As[(acg + 0) * AP + arow0] = av0.x;
        As[(acg + 1) * AP + arow0] = av0.y;
        As[(acg + 2) * AP + arow0] = av0.z;
        As[(acg + 3) * AP + arow0] = av0.w;
        As[(acg + 0) * AP + arow1] = av1.x;
        As[(acg + 1) * AP + arow1] = av1.y;
        As[(acg + 2) * AP + arow1] = av1.z;
        As[(acg + 3) * AP + arow1] = av1.w;
        *(float4*)&Bs[brow * BP + bc]       = bv0;
        *(float4*)&Bs[(brow + 8) * BP + bc] = bv1;
        __syncthreads();
        #pragma unroll
        for (int k = 0; k < BKK; k++) {
            float4 aA = *(const float4*)&As[k * AP + ty * 8];
            float4 aB = *(const float4*)&As[k * AP + ty * 8 + 4];
            float4 bA = *(const float4*)&Bs[k * BP + tx * 8];
            float4 bB = *(const float4*)&Bs[k * BP + tx * 8 + 4];
            float a[8] = {aA.x, aA.y, aA.z, aA.w, aB.x, aB.y, aB.z, aB.w};
            float b[8] = {bA.x, bA.y, bA.z, bA.w, bB.x, bB.y, bB.z, bB.w};
            #pragma unroll
            for (int i = 0; i < 8; i++)
                #pragma unroll
                for (int j = 0; j < 8; j++) c[i][j] += a[i] * b[j];
        }
    }

    // epilogue: bias + relu, store to compacted h buffer
    float bias[8];
    #pragma unroll
    for (int j = 0; j < 8; j++) bias[j] = b1[(size_t)e * HDIM + n0 + tx * 8 + j];
    #pragma unroll
    for (int i = 0; i < 8; i++) {
        int m = m0 + ty * 8 + i;
        if (m < cnt) {
            float* hr = g_hbuf + (size_t)(off + m) * HDIM + n0 + tx * 8;
            float4 v0, v1;
            v0.x = fmaxf(c[i][0] + bias[0], 0.f);
            v0.y = fmaxf(c[i][1] + bias[1], 0.f);
            v0.z = fmaxf(c[i][2] + bias[2], 0.f);
            v0.w = fmaxf(c[i][3] + bias[3], 0.f);
            v1.x = fmaxf(c[i][4] + bias[4], 0.f);
            v1.y = fmaxf(c[i][5] + bias[5], 0.f);
            v1.z = fmaxf(c[i][6] + bias[6], 0.f);
            v1.w = fmaxf(c[i][7] + bias[7], 0.f);
            *(float4*)(hr)     = v0;
            *(float4*)(hr + 4) = v1;
        }
    }
}

// GEMM2: out[token] += gate * ( h @ w2[e] + b2[e] )   M=count[e], N=512, K=2048
__global__ __launch_bounds__(256, 2)
void gemm2_kernel(const float* __restrict__ w2,
                  const float* __restrict__ b2,
                  float* __restrict__ out) {
    int e   = blockIdx.z;
    int cnt = g_counts[e];
    int m0  = blockIdx.y * BM;
    if (m0 >= cnt) return;
    int n0  = blockIdx.x * BN;
    int off = g_offsets[e];
    const float* Bw = w2 + (size_t)e * HDIM * DDIM;

    __shared__ float As[BKK * AP];
    __shared__ float Bs[BKK * BP];

    int tid = threadIdx.x;
    int arow0 = tid >> 2;
    int arow1 = arow0 + 64;
    int acg   = (tid & 3) * 4;
    int mr0 = m0 + arow0; if (mr0 > cnt - 1) mr0 = cnt - 1;
    int mr1 = m0 + arow1; if (mr1 > cnt - 1) mr1 = cnt - 1;
    const float* a0p = g_hbuf + (size_t)(off + mr0) * HDIM + acg;
    const float* a1p = g_hbuf + (size_t)(off + mr1) * HDIM + acg;

    int brow = tid >> 5;
    int bc   = (tid & 31) * 4;
    const float* b0p = Bw + (size_t)brow * DDIM + n0 + bc;
    const float* b1p = b0p + (size_t)8 * DDIM;

    int tx = tid & 15, ty = tid >> 4;
    float c[8][8];
    #pragma unroll
    for (int i = 0; i < 8; i++)
        #pragma unroll
        for (int j = 0; j < 8; j++) c[i][j] = 0.f;

    for (int k0 = 0; k0 < HDIM; k0 += BKK) {
        float4 av0 = *(const float4*)(a0p + k0);
        float4 av1 = *(const float4*)(a1p + k0);
        float4 bv0 = *(const float4*)(b0p + (size_t)k0 * DDIM);
        float4 bv1 = *(const float4*)(b1p + (size_t)k0 * DDIM);
        __syncthreads();
        As[(acg + 0) * AP + arow0] = av0.x;
        As[(acg + 1) * AP + arow0] = av0.y;
        As[(acg + 2) * AP + arow0] = av0.z;
        As[(acg + 3) * AP + arow0] = av0.w;
        As[(acg + 0) * AP + arow1] = av1.x;
        As[(acg + 1) * AP + arow1] = av1.y;
        As[(acg + 2) * AP + arow1] = av1.z;
        As[(acg + 3) * AP + arow1] = av1.w;
        *(float4*)&Bs[brow * BP + bc]       = bv0;
        *(float4*)&Bs[(brow + 8) * BP + bc] = bv1;
        __syncthreads();
        #pragma unroll
        for (int k = 0; k < BKK; k++) {
            float4 aA = *(const float4*)&As[k * AP + ty * 8];
            float4 aB = *(const float4*)&As[k * AP + ty * 8 + 4];
            float4 bA = *(const float4*)&Bs[k * BP + tx * 8];
            float4 bB = *(const float4*)&Bs[k * BP + tx * 8 + 4];
            float a[8] = {aA.x, aA.y, aA.z, aA.w, aB.x, aB.y, aB.z, aB.w};
            float b[8] = {bA.x, bA.y, bA.z, bA.w, bB.x, bB.y, bB.z, bB.w};
            #pragma unroll
            for (int i = 0; i < 8; i++)
                #pragma unroll
                for (int j = 0; j < 8; j++) c[i][j] += a[i] * b[j];
        }
    }

    // epilogue: gate-scale, bias, scatter-add into out (2 commutative adds/token)
    float bias[8];
    #pragma unroll
    for (int j = 0; j < 8; j++) bias[j] = b2[(size_t)e * DDIM + n0 + tx * 8 + j];
    #pragma unroll
    for (int i = 0; i < 8; i++) {
        int m = m0 + ty * 8 + i;
        if (m < cnt) {
            int   tok  = g_tokens[e * CAP + m];
            float gate = g_gates[e * CAP + m];
            float* orow = out + (size_t)tok * DDIM + n0 + tx * 8;
            #pragma unroll
            for (int j = 0; j < 8; j++)
                atomicAdd(&orow[j], gate * (c[i][j] + bias[j]));
        }
    }
}

// ---------------- launch ------------------------------------------------------
extern "C" void kernel_launch(void* const* d_in, const int* in_sizes, int n_in,
                              void* d_out, int out_size) {
    const float* x   = (const float*)d_in[0];   // [65536,512]
    const float* rw  = (const float*)d_in[1];   // [512,8]
    const float* rb  = (const float*)d_in[2];   // [8]
    const float* w1  = (const float*)d_in[3];   // [8,512,2048]
    const float* b1  = (const float*)d_in[4];   // [8,2048]
    const float* w2  = (const float*)d_in[5];   // [8,2048,512]
    const float* b2  = (const float*)d_in[6];   // [8,512]
    float*       out = (float*)d_out;           // [65536,512]

    cudaMemsetAsync(out, 0, (size_t)out_size * sizeof(float));
    zero_counts_kernel<<<1, 32>>>();
    router_kernel<<<TOKENS / 8, 256>>>(x, rw, rb);
    offsets_kernel<<<1, 32>>>();

    dim3 g1(HDIM / BN, (CAP + BM - 1) / BM, NEXP);   // (16, 512, 8)
    gemm1_kernel<<<g1, 256>>>(x, w1, b1);

    dim3 g2(DDIM / BN, (CAP + BM - 1) / BM, NEXP);   // (4, 512, 8)
    gemm2_kernel<<<g2, 256>>>(w2, b2, out);
}

// round 4
// speedup vs baseline: 2.2544x; 2.2544x over previous
#include <cuda_runtime.h>
#include <cuda_bf16.h>
#include <math.h>
#include <stdint.h>

#define TOKENS 65536
#define DDIM   512
#define NEXP   8
#define HDIM   2048
#define CAP    65536

// ---------------- device scratch (no allocs allowed) -------------------------
__device__ int   g_counts [NEXP];
__device__ int   g_offsets[NEXP];
__device__ int   g_tokens [NEXP * CAP];   // token*2 + slot
__device__ float g_gates  [NEXP * CAP];
__device__ __nv_bfloat16 g_x_hi [(size_t)TOKENS * DDIM];
__device__ __nv_bfloat16 g_x_lo [(size_t)TOKENS * DDIM];
__device__ __nv_bfloat16 g_w1t_hi[(size_t)NEXP * HDIM * DDIM];  // [E][H][D] K-major
__device__ __nv_bfloat16 g_w1t_lo[(size_t)NEXP * HDIM * DDIM];
__device__ __nv_bfloat16 g_w2t_hi[(size_t)NEXP * DDIM * HDIM];  // [E][D][H] K-major
__device__ __nv_bfloat16 g_w2t_lo[(size_t)NEXP * DDIM * HDIM];
__device__ __nv_bfloat16 g_h_hi[(size_t)2 * TOKENS * HDIM];     // compact hidden
__device__ __nv_bfloat16 g_h_lo[(size_t)2 * TOKENS * HDIM];
__device__ float g_y[(size_t)2 * TOKENS * DDIM];                // slot outputs

// ---------------- helpers -----------------------------------------------------
__device__ __forceinline__ uint32_t smem_u32(const void* p) {
    uint32_t a;
    asm("{ .reg .u64 t; cvta.to.shared.u64 t, %1; cvt.u32.u64 %0, t; }" : "=r"(a) : "l"(p));
    return a;
}
__device__ __forceinline__ void ldsm4(uint32_t* r, uint32_t addr) {
    asm volatile("ldmatrix.sync.aligned.m8n8.x4.shared.b16 {%0,%1,%2,%3}, [%4];"
        : "=r"(r[0]), "=r"(r[1]), "=r"(r[2]), "=r"(r[3]) : "r"(addr));
}
__device__ __forceinline__ void mma16816(float* c, const uint32_t* a, const uint32_t* b) {
    asm volatile(
        "mma.sync.aligned.m16n8k16.row.col.f32.bf16.bf16.f32 "
        "{%0,%1,%2,%3}, {%4,%5,%6,%7}, {%8,%9}, {%0,%1,%2,%3};"
        : "+f"(c[0]), "+f"(c[1]), "+f"(c[2]), "+f"(c[3])
        : "r"(a[0]), "r"(a[1]), "r"(a[2]), "r"(a[3]), "r"(b[0]), "r"(b[1]));
}
#define CPA(dst, src) \
    asm volatile("cp.async.cg.shared.global [%0], [%1], 16;" :: "r"(dst), "l"(src) : "memory")
#define CPC() asm volatile("cp.async.commit_group;" ::: "memory")
#define CPW1() asm volatile("cp.async.wait_group 1;" ::: "memory")

__device__ __forceinline__ void split2(float v, __nv_bfloat16& h, __nv_bfloat16& l) {
    h = __float2bfloat16_rn(v);
    l = __float2bfloat16_rn(v - __bfloat162float(h));
}
__device__ __forceinline__ uint32_t pack2(__nv_bfloat16 a, __nv_bfloat16 b) {
    union { __nv_bfloat16 h[2]; uint32_t u; } t;
    t.h[0] = a; t.h[1] = b;
    return t.u;
}

// ---------------- prep kernels ------------------------------------------------
__global__ void zero_counts_kernel() { if (threadIdx.x < NEXP) g_counts[threadIdx.x] = 0; }

__global__ void offsets_kernel() {
    if (threadIdx.x == 0) {
        int s = 0;
        #pragma unroll
        for (int e = 0; e < NEXP; e++) { g_offsets[e] = s; s += g_counts[e]; }
    }
}

__global__ void split_x_kernel(const float* __restrict__ x) {
    size_t i = ((size_t)blockIdx.x * 256 + threadIdx.x) * 4;
    float4 v = *(const float4*)(x + i);
    __nv_bfloat16 h0, l0, h1, l1, h2, l2, h3, l3;
    split2(v.x, h0, l0); split2(v.y, h1, l1);
    split2(v.z, h2, l2); split2(v.w, h3, l3);
    uint2 H, L;
    H.x = pack2(h0, h1); H.y = pack2(h2, h3);
    L.x = pack2(l0, l1); L.y = pack2(l2, l3);
    *(uint2*)(g_x_hi + i) = H;
    *(uint2*)(g_x_lo + i) = L;
}

// transpose [R][C] fp32 (per expert) -> [C][R] bf16 hi/lo
template<int SEL>   // 0: w1 (R=512,C=2048), 1: w2 (R=2048,C=512)
__global__ void tsplit_kernel(const float* __restrict__ src) {
    constexpr int R = SEL ? HDIM : DDIM;
    constexpr int C = SEL ? DDIM : HDIM;
    __nv_bfloat16* dh = SEL ? g_w2t_hi : g_w1t_hi;
    __nv_bfloat16* dl = SEL ? g_w2t_lo : g_w1t_lo;
    __shared__ float t[32][33];
    int e = blockIdx.z;
    const float* s = src + (size_t)e * R * C;
    int c0 = blockIdx.x * 32, r0 = blockIdx.y * 32;
    int tx = threadIdx.x, ty = threadIdx.y;
    #pragma unroll
    for (int j = 0; j < 4; j++)
        t[ty + j * 8][tx] = s[(size_t)(r0 + ty + j * 8) * C + c0 + tx];
    __syncthreads();
    #pragma unroll
    for (int j = 0; j < 4; j++) {
        float v = t[tx][ty + j * 8];
        __nv_bfloat16 h, l; split2(v, h, l);
        size_t o = ((size_t)e * C + c0 + ty + j * 8) * R + r0 + tx;
        dh[o] = h; dl[o] = l;
    }
}

// ---------------- router ------------------------------------------------------
__global__ void router_kernel(const float* __restrict__ x,
                              const float* __restrict__ rw,
                              const float* __restrict__ rb) {
    __shared__ float srw[DDIM * NEXP];
    int tid = threadIdx.x;
    for (int i = tid; i < DDIM * NEXP; i += blockDim.x) srw[i] = rw[i];
    __syncthreads();
    int warp = tid >> 5, lane = tid & 31;
    int t = blockIdx.x * 8 + warp;
    const float* xr = x + (size_t)t * DDIM;
    float acc[NEXP];
    #pragma unroll
    for (int e = 0; e < NEXP; e++) acc[e] = 0.f;
    for (int d = lane; d < DDIM; d += 32) {
        float xv = xr[d];
        #pragma unroll
        for (int e = 0; e < NEXP; e++) acc[e] += xv * srw[d * NEXP + e];
    }
    #pragma unroll
    for (int e = 0; e < NEXP; e++) {
        #pragma unroll
        for (int o = 16; o > 0; o >>= 1)
            acc[e] += __shfl_xor_sync(0xffffffffu, acc[e], o);
    }
    if (lane == 0) {
        float l[NEXP];
        #pragma unroll
        for (int e = 0; e < NEXP; e++) l[e] = acc[e] + rb[e];
        int e1 = 0;
        #pragma unroll
        for (int e = 1; e < NEXP; e++) if (l[e] > l[e1]) e1 = e;
        int e2 = (e1 == 0) ? 1 : 0;
        #pragma unroll
        for (int e = 0; e < NEXP; e++)
            if (e != e1 && l[e] > l[e2]) e2 = e;
        float d2 = expf(l[e2] - l[e1]);
        float g2 = d2 / (1.f + d2);
        float g1 = 1.f - g2;
        int p1 = atomicAdd(&g_counts[e1], 1);
        g_tokens[e1 * CAP + p1] = t * 2 + 0;  g_gates[e1 * CAP + p1] = g1;
        int p2 = atomicAdd(&g_counts[e2], 1);
        g_tokens[e2 * CAP + p2] = t * 2 + 1;  g_gates[e2 * CAP + p2] = g2;
    }
}

// ---------------- HMMA GEMM ---------------------------------------------------
// Tile 128x128x32, bf16 hi/lo (3-term split), cp.async 2-stage double buffer.
// SMEM stage: Ah(10240) Al(10240) Bh(10240) Bl(10240) = 40960B; rows padded to 80B.
#define STG   40960
#define DSMEM (2 * STG)

template<bool G1>
__global__ void __launch_bounds__(256, 2)
hgemm_kernel(const float* __restrict__ bias_vec) {
    constexpr int KTOT = G1 ? DDIM : HDIM;
    constexpr int NTOT = G1 ? HDIM : DDIM;
    constexpr int NC   = KTOT / 32;

    int e   = blockIdx.z;
    int cnt = g_counts[e];
    int m0  = blockIdx.y * 128;
    if (m0 >= cnt) return;
    int n0  = blockIdx.x * 128;
    int off = g_offsets[e];

    extern __shared__ char dsm[];
    __shared__ int   s_tok[128];
    __shared__ float s_gate[128];
    __shared__ float s_bias[128];

    int tid = threadIdx.x;
    int lane = tid & 31, wid = tid >> 5;

    if (tid < 128) {
        int m = m0 + tid; if (m > cnt - 1) m = cnt - 1;
        s_tok[tid]  = g_tokens[e * CAP + m];
        s_gate[tid] = g_gates [e * CAP + m];
        s_bias[tid] = bias_vec[(size_t)e * NTOT + n0 + tid];
    }
    __syncthreads();

    const __nv_bfloat16* Ahi = G1 ? g_x_hi : g_h_hi;
    const __nv_bfloat16* Alo = G1 ? g_x_lo : g_h_lo;
    const __nv_bfloat16* Bhi = G1 ? g_w1t_hi : g_w2t_hi;
    const __nv_bfloat16* Blo = G1 ? g_w1t_lo : g_w2t_lo;

    // ---- cp.async mapping: thread t -> row t/2, 32B half (t&1) of 64B row ----
    int r    = tid >> 1;
    int eoff = (tid & 1) * 16;             // element offset (16 bf16 = 32B)
    size_t aRow;
    if (G1) aRow = (size_t)(s_tok[r] >> 1) * DDIM;
    else {
        int mm = m0 + r; if (mm > cnt - 1) mm = cnt - 1;
        aRow = (size_t)(off + mm) * HDIM;
    }
    const __nv_bfloat16* aH = Ahi + aRow + eoff;
    const __nv_bfloat16* aL = Alo + aRow + eoff;
    size_t bRow = ((size_t)e * NTOT + n0 + r) * KTOT;
    const __nv_bfloat16* bH = Bhi + bRow + eoff;
    const __nv_bfloat16* bL = Blo + bRow + eoff;

    uint32_t sb = smem_u32(dsm);
    uint32_t dA = sb + 80 * r + 32 * (tid & 1);
    uint32_t dB = dA + 20480;

    // ---- ldmatrix base addresses ----
    int wm = wid & 3, wn = wid >> 2;       // warp tile: rows wm*32, cols wn*64
    uint32_t aOff = sb + 80 * (wm * 32 + (lane & 15)) + 16 * (lane >> 4);
    uint32_t bOff = sb + 20480 +
                    80 * (wn * 64 + (lane & 7) + 8 * (lane >> 4)) +
                    16 * ((lane >> 3) & 1);

    float c[2][8][4];
    #pragma unroll
    for (int i = 0; i < 2; i++)
        #pragma unroll
        for (int j = 0; j < 8; j++)
            #pragma unroll
            for (int q = 0; q < 4; q++) c[i][j][q] = 0.f;

    // ---- prologue: chunks 0,1 ----
    #pragma unroll
    for (int i = 0; i < 2; i++) {
        uint32_t st = i * STG;
        int k0 = i * 32;
        CPA(dA + st,             aH + k0);  CPA(dA + st + 16,         aH + k0 + 8);
        CPA(dA + st + 10240,     aL + k0);  CPA(dA + st + 10240 + 16, aL + k0 + 8);
        CPA(dB + st,             bH + k0);  CPA(dB + st + 16,         bH + k0 + 8);
        CPA(dB + st + 10240,     bL + k0);  CPA(dB + st + 10240 + 16, bL + k0 + 8);
        CPC();
    }

    for (int i = 0; i < NC; i++) {
        CPW1();
        __syncthreads();
        uint32_t st = (i & 1) * STG;
        #pragma unroll
        for (int kk = 0; kk < 2; kk++) {
            uint32_t ah[2][4], al[2][4];
            ldsm4(ah[0], aOff + st + kk * 32);
            ldsm4(ah[1], aOff + st + kk * 32 + 1280);
            ldsm4(al[0], aOff + st + kk * 32 + 10240);
            ldsm4(al[1], aOff + st + kk * 32 + 10240 + 1280);
            #pragma unroll
            for (int ng = 0; ng < 4; ng++) {
                uint32_t bh[4], bl[4];
                ldsm4(bh, bOff + st + ng * 1280 + kk * 32);
                ldsm4(bl, bOff + st + ng * 1280 + kk * 32 + 10240);
                #pragma unroll
                for (int mi = 0; mi < 2; mi++) {
                    mma16816(c[mi][2 * ng],     ah[mi], bh);
                    mma16816(c[mi][2 * ng],     al[mi], bh);
                    mma16816(c[mi][2 * ng],     ah[mi], bl);
                    mma16816(c[mi][2 * ng + 1], ah[mi], bh + 2);
                    mma16816(c[mi][2 * ng + 1], al[mi], bh + 2);
                    mma16816(c[mi][2 * ng + 1], ah[mi], bl + 2);
                }
            }
        }
        __syncthreads();
        if (i + 2 < NC) {
            int k0 = (i + 2) * 32;
            CPA(dA + st,             aH + k0);  CPA(dA + st + 16,         aH + k0 + 8);
            CPA(dA + st + 10240,     aL + k0);  CPA(dA + st + 10240 + 16, aL + k0 + 8);
            CPA(dB + st,             bH + k0);  CPA(dB + st + 16,         bH + k0 + 8);
            CPA(dB + st + 10240,     bL + k0);  CPA(dB + st + 10240 + 16, bL + k0 + 8);
        }
        CPC();
    }

    // ---- epilogue: stage C in smem (pitch 132 floats), then coalesced out ----
    __syncthreads();
    float* sC = (float*)dsm;
    #pragma unroll
    for (int mi = 0; mi < 2; mi++) {
        #pragma unroll
        for (int nf = 0; nf < 8; nf++) {
            int rm = wm * 32 + mi * 16 + (lane >> 2);
            int cn = wn * 64 + nf * 8 + 2 * (lane & 3);
            *(float2*)&sC[rm * 132 + cn]       = make_float2(c[mi][nf][0], c[mi][nf][1]);
            *(float2*)&sC[(rm + 8) * 132 + cn] = make_float2(c[mi][nf][2], c[mi][nf][3]);
        }
    }
    __syncthreads();

    int rr = tid >> 1;
    int cb = (tid & 1) * 64;
    bool mv = (m0 + rr) < cnt;
    if (G1) {
        if (mv) {
            size_t rowb = (size_t)(off + m0 + rr) * HDIM + n0 + cb;
            #pragma unroll
            for (int g = 0; g < 8; g++) {
                uint32_t H[4], L[4];
                #pragma unroll
                for (int p = 0; p < 4; p++) {
                    int col = cb + g * 8 + 2 * p;
                    float v0 = fmaxf(sC[rr * 132 + col]     + s_bias[col],     0.f);
                    float v1 = fmaxf(sC[rr * 132 + col + 1] + s_bias[col + 1], 0.f);
                    __nv_bfloat16 h0, l0, h1, l1;
                    split2(v0, h0, l0); split2(v1, h1, l1);
                    H[p] = pack2(h0, h1); L[p] = pack2(l0, l1);
                }
                *(uint4*)(g_h_hi + rowb + g * 8) = *(uint4*)H;
                *(uint4*)(g_h_lo + rowb + g * 8) = *(uint4*)L;
            }
        }
    } else {
        if (mv) {
            int enc  = s_tok[rr];
            int tok  = enc >> 1, slot = enc & 1;
            float gt = s_gate[rr];
            float* dst = g_y + ((size_t)slot * TOKENS + tok) * DDIM + n0 + cb;
            #pragma unroll
            for (int g = 0; g < 16; g++) {
                int col = cb + g * 4;
                float4 o;
                o.x = gt * (sC[rr * 132 + col]     + s_bias[col]);
                o.y = gt * (sC[rr * 132 + col + 1] + s_bias[col + 1]);
                o.z = gt * (sC[rr * 132 + col + 2] + s_bias[col + 2]);
                o.w = gt * (sC[rr * 132 + col + 3] + s_bias[col + 3]);
                *(float4*)(dst + g * 4) = o;
            }
        }
    }
}

__global__ void combine_kernel(float* __restrict__ out) {
    size_t i = ((size_t)blockIdx.x * 256 + threadIdx.x) * 4;
    float4 a = *(const float4*)(g_y + i);
    float4 b = *(const float4*)(g_y + (size_t)TOKENS * DDIM + i);
    float4 o;
    o.x = a.x + b.x; o.y = a.y + b.y; o.z = a.z + b.z; o.w = a.w + b.w;
    *(float4*)(out + i) = o;
}

// ---------------- launch ------------------------------------------------------
extern "C" void kernel_launch(void* const* d_in, const int* in_sizes, int n_in,
                              void* d_out, int out_size) {
    const float* x   = (const float*)d_in[0];
    const float* rw  = (const float*)d_in[1];
    const float* rb  = (const float*)d_in[2];
    const float* w1  = (const float*)d_in[3];
    const float* b1  = (const float*)d_in[4];
    const float* w2  = (const float*)d_in[5];
    const float* b2  = (const float*)d_in[6];
    float*       out = (float*)d_out;

    cudaFuncSetAttribute(hgemm_kernel<true>,
                         cudaFuncAttributeMaxDynamicSharedMemorySize, DSMEM);
    cudaFuncSetAttribute(hgemm_kernel<false>,
                         cudaFuncAttributeMaxDynamicSharedMemorySize, DSMEM);

    zero_counts_kernel<<<1, 32>>>();
    router_kernel<<<TOKENS / 8, 256>>>(x, rw, rb);
    offsets_kernel<<<1, 32>>>();

    split_x_kernel<<<TOKENS * DDIM / 1024, 256>>>(x);
    tsplit_kernel<0><<<dim3(HDIM / 32, DDIM / 32, NEXP), dim3(32, 8)>>>(w1);
    tsplit_kernel<1><<<dim3(DDIM / 32, HDIM / 32, NEXP), dim3(32, 8)>>>(w2);

    hgemm_kernel<true ><<<dim3(HDIM / 128, CAP / 128, NEXP), 256, DSMEM>>>(b1);
    hgemm_kernel<false><<<dim3(DDIM / 128, CAP / 128, NEXP), 256, DSMEM>>>(b2);

    combine_kernel<<<TOKENS * DDIM / 1024, 256>>>(out);
}

// round 5
// speedup vs baseline: 3.0443x; 1.3504x over previous
#include <cuda_runtime.h>
#include <cuda_fp16.h>
#include <math.h>
#include <stdint.h>

#define TOKENS 65536
#define DDIM   512
#define NEXP   8
#define HDIM   2048
#define CAP    65536

// ---------------- device scratch (no allocs allowed) -------------------------
__device__ int   g_counts [NEXP];
__device__ int   g_offsets[NEXP];
__device__ int   g_tokens [NEXP * CAP];   // token*2 + slot
__device__ float g_gates  [NEXP * CAP];
__device__ __half g_x_hi [(size_t)TOKENS * DDIM];
__device__ __half g_x_lo [(size_t)TOKENS * DDIM];
__device__ __half g_w1t  [(size_t)NEXP * HDIM * DDIM];   // [E][H][D] K-major fp16
__device__ __half g_w2t_hi[(size_t)NEXP * DDIM * HDIM];  // [E][D][H] K-major
__device__ __half g_w2t_lo[(size_t)NEXP * DDIM * HDIM];
__device__ __half g_h[(size_t)2 * TOKENS * HDIM];        // compact hidden fp16
__device__ float g_y[(size_t)2 * TOKENS * DDIM];         // slot outputs

// ---------------- helpers -----------------------------------------------------
__device__ __forceinline__ uint32_t smem_u32(const void* p) {
    uint32_t a;
    asm("{ .reg .u64 t; cvta.to.shared.u64 t, %1; cvt.u32.u64 %0, t; }" : "=r"(a) : "l"(p));
    return a;
}
__device__ __forceinline__ void ldsm4(uint32_t* r, uint32_t addr) {
    asm volatile("ldmatrix.sync.aligned.m8n8.x4.shared.b16 {%0,%1,%2,%3}, [%4];"
        : "=r"(r[0]), "=r"(r[1]), "=r"(r[2]), "=r"(r[3]) : "r"(addr));
}
__device__ __forceinline__ void mma16816(float* c, const uint32_t* a, const uint32_t* b) {
    asm volatile(
        "mma.sync.aligned.m16n8k16.row.col.f32.f16.f16.f32 "
        "{%0,%1,%2,%3}, {%4,%5,%6,%7}, {%8,%9}, {%0,%1,%2,%3};"
        : "+f"(c[0]), "+f"(c[1]), "+f"(c[2]), "+f"(c[3])
        : "r"(a[0]), "r"(a[1]), "r"(a[2]), "r"(a[3]), "r"(b[0]), "r"(b[1]));
}
#define CPA(dst, src) \
    asm volatile("cp.async.cg.shared.global [%0], [%1], 16;" :: "r"(dst), "l"(src) : "memory")
#define CPC()  asm volatile("cp.async.commit_group;" ::: "memory")
#define CPW1() asm volatile("cp.async.wait_group 1;" ::: "memory")

__device__ __forceinline__ void hsplit(float v, __half& h, __half& l) {
    h = __float2half_rn(v);
    l = __float2half_rn(v - __half2float(h));
}
__device__ __forceinline__ uint32_t hpack2(__half a, __half b) {
    union { __half h[2]; uint32_t u; } t;
    t.h[0] = a; t.h[1] = b;
    return t.u;
}

// ---------------- prep kernels ------------------------------------------------
__global__ void zero_counts_kernel() { if (threadIdx.x < NEXP) g_counts[threadIdx.x] = 0; }

__global__ void offsets_kernel() {
    if (threadIdx.x == 0) {
        int s = 0;
        #pragma unroll
        for (int e = 0; e < NEXP; e++) { g_offsets[e] = s; s += g_counts[e]; }
    }
}

__global__ void split_x_kernel(const float* __restrict__ x) {
    size_t i = ((size_t)blockIdx.x * 256 + threadIdx.x) * 4;
    float4 v = *(const float4*)(x + i);
    __half h0, l0, h1, l1, h2, l2, h3, l3;
    hsplit(v.x, h0, l0); hsplit(v.y, h1, l1);
    hsplit(v.z, h2, l2); hsplit(v.w, h3, l3);
    uint2 H, L;
    H.x = hpack2(h0, h1); H.y = hpack2(h2, h3);
    L.x = hpack2(l0, l1); L.y = hpack2(l2, l3);
    *(uint2*)(g_x_hi + i) = H;
    *(uint2*)(g_x_lo + i) = L;
}

// w1: [512][2048] fp32 -> [2048][512] fp16 (single)
__global__ void t_w1_kernel(const float* __restrict__ src) {
    __shared__ float t[32][33];
    int e = blockIdx.z;
    const float* s = src + (size_t)e * DDIM * HDIM;
    int c0 = blockIdx.x * 32, r0 = blockIdx.y * 32;
    int tx = threadIdx.x, ty = threadIdx.y;
    #pragma unroll
    for (int j = 0; j < 4; j++)
        t[ty + j * 8][tx] = s[(size_t)(r0 + ty + j * 8) * HDIM + c0 + tx];
    __syncthreads();
    #pragma unroll
    for (int j = 0; j < 4; j++) {
        float v = t[tx][ty + j * 8];
        size_t o = ((size_t)e * HDIM + c0 + ty + j * 8) * DDIM + r0 + tx;
        g_w1t[o] = __float2half_rn(v);
    }
}

// w2: [2048][512] fp32 -> [512][2048] fp16 hi/lo
__global__ void t_w2_kernel(const float* __restrict__ src) {
    __shared__ float t[32][33];
    int e = blockIdx.z;
    const float* s = src + (size_t)e * HDIM * DDIM;
    int c0 = blockIdx.x * 32, r0 = blockIdx.y * 32;
    int tx = threadIdx.x, ty = threadIdx.y;
    #pragma unroll
    for (int j = 0; j < 4; j++)
        t[ty + j * 8][tx] = s[(size_t)(r0 + ty + j * 8) * DDIM + c0 + tx];
    __syncthreads();
    #pragma unroll
    for (int j = 0; j < 4; j++) {
        float v = t[tx][ty + j * 8];
        __half h, l; hsplit(v, h, l);
        size_t o = ((size_t)e * DDIM + c0 + ty + j * 8) * HDIM + r0 + tx;
        g_w2t_hi[o] = h; g_w2t_lo[o] = l;
    }
}

// ---------------- router ------------------------------------------------------
__global__ void router_kernel(const float* __restrict__ x,
                              const float* __restrict__ rw,
                              const float* __restrict__ rb) {
    __shared__ float srw[DDIM * NEXP];
    int tid = threadIdx.x;
    for (int i = tid; i < DDIM * NEXP; i += blockDim.x) srw[i] = rw[i];
    __syncthreads();
    int warp = tid >> 5, lane = tid & 31;
    int t = blockIdx.x * 8 + warp;
    const float* xr = x + (size_t)t * DDIM;
    float acc[NEXP];
    #pragma unroll
    for (int e = 0; e < NEXP; e++) acc[e] = 0.f;
    for (int d = lane; d < DDIM; d += 32) {
        float xv = xr[d];
        #pragma unroll
        for (int e = 0; e < NEXP; e++) acc[e] += xv * srw[d * NEXP + e];
    }
    #pragma unroll
    for (int e = 0; e < NEXP; e++) {
        #pragma unroll
        for (int o = 16; o > 0; o >>= 1)
            acc[e] += __shfl_xor_sync(0xffffffffu, acc[e], o);
    }
    if (lane == 0) {
        float l[NEXP];
        #pragma unroll
        for (int e = 0; e < NEXP; e++) l[e] = acc[e] + rb[e];
        int e1 = 0;
        #pragma unroll
        for (int e = 1; e < NEXP; e++) if (l[e] > l[e1]) e1 = e;
        int e2 = (e1 == 0) ? 1 : 0;
        #pragma unroll
        for (int e = 0; e < NEXP; e++)
            if (e != e1 && l[e] > l[e2]) e2 = e;
        float d2 = expf(l[e2] - l[e1]);
        float g2 = d2 / (1.f + d2);
        float g1 = 1.f - g2;
        int p1 = atomicAdd(&g_counts[e1], 1);
        g_tokens[e1 * CAP + p1] = t * 2 + 0;  g_gates[e1 * CAP + p1] = g1;
        int p2 = atomicAdd(&g_counts[e2], 1);
        g_tokens[e2 * CAP + p2] = t * 2 + 1;  g_gates[e2 * CAP + p2] = g2;
    }
}

// ---------------- HMMA GEMM ---------------------------------------------------
// Tile 128x128x32, fp16 asymmetric 2-term split, 3-stage cp.async pipeline.
// Stage: 3 arrays x (128 rows x 80B) = 30720B.
//   G1: A_hi @0, A_lo @10240, B @20480
//   G2: A    @0, B_hi @10240, B_lo @20480
#define STG   30720
#define NSTG  3
#define DSMEM (NSTG * STG)

template<bool G1>
__global__ void __launch_bounds__(256, 2)
hgemm_kernel(const float* __restrict__ bias_vec) {
    constexpr int KTOT = G1 ? DDIM : HDIM;
    constexpr int NTOT = G1 ? HDIM : DDIM;
    constexpr int NC   = KTOT / 32;

    int e   = blockIdx.z;
    int cnt = g_counts[e];
    int m0  = blockIdx.y * 128;
    if (m0 >= cnt) return;
    int n0  = blockIdx.x * 128;
    int off = g_offsets[e];

    extern __shared__ char dsm[];
    __shared__ int   s_tok[128];
    __shared__ float s_gate[128];
    __shared__ float s_bias[128];

    int tid = threadIdx.x;
    int lane = tid & 31, wid = tid >> 5;

    if (tid < 128) {
        int m = m0 + tid; if (m > cnt - 1) m = cnt - 1;
        s_tok[tid]  = g_tokens[e * CAP + m];
        s_gate[tid] = g_gates [e * CAP + m];
        s_bias[tid] = bias_vec[(size_t)e * NTOT + n0 + tid];
    }
    __syncthreads();

    // ---- cp.async mapping: thread t -> row t/2, 32B half (t&1) of 64B row ----
    int r    = tid >> 1;
    int eoff = (tid & 1) * 16;
    size_t aRow;
    if (G1) aRow = (size_t)(s_tok[r] >> 1) * DDIM;
    else {
        int mm = m0 + r; if (mm > cnt - 1) mm = cnt - 1;
        aRow = (size_t)(off + mm) * HDIM;
    }
    const __half* a0 = (G1 ? g_x_hi : g_h) + aRow + eoff;          // slot 0
    const __half* a1 = G1 ? (g_x_lo + aRow + eoff) : (const __half*)0;
    size_t bRow = ((size_t)e * NTOT + n0 + r) * KTOT + eoff;
    const __half* b0 = (G1 ? g_w1t : g_w2t_hi) + bRow;
    const __half* b1 = G1 ? (const __half*)0 : (g_w2t_lo + bRow);

    uint32_t sb = smem_u32(dsm);
    uint32_t d0 = sb + 80 * r + 32 * (tid & 1);                    // array 0
    // G1: arr1 = A_lo (+10240), arr2 = B (+20480)
    // G2: arr1 = B_hi (+10240), arr2 = B_lo (+20480)

    // ---- ldmatrix base addresses ----
    int wm = wid & 3, wn = wid >> 2;
    uint32_t aOff = sb + 80 * (wm * 32 + (lane & 15)) + 16 * (lane >> 4);
    uint32_t bOff = sb + (G1 ? 20480 : 10240) +
                    80 * (wn * 64 + (lane & 7) + 8 * (lane >> 4)) +
                    16 * ((lane >> 3) & 1);

    float c[2][8][4];
    #pragma unroll
    for (int i = 0; i < 2; i++)
        #pragma unroll
        for (int j = 0; j < 8; j++)
            #pragma unroll
            for (int q = 0; q < 4; q++) c[i][j][q] = 0.f;

    // ---- prologue: stages 0,1 ----
    #pragma unroll
    for (int i = 0; i < 2; i++) {
        uint32_t st = i * STG;
        int k0 = i * 32;
        CPA(d0 + st,             a0 + k0);  CPA(d0 + st + 16,         a0 + k0 + 8);
        if (G1) { CPA(d0 + st + 10240, a1 + k0); CPA(d0 + st + 10240 + 16, a1 + k0 + 8); }
        CPA(d0 + st + (G1 ? 20480 : 10240),      b0 + k0);
        CPA(d0 + st + (G1 ? 20480 : 10240) + 16, b0 + k0 + 8);
        if (!G1) { CPA(d0 + st + 20480, b1 + k0); CPA(d0 + st + 20480 + 16, b1 + k0 + 8); }
        CPC();
    }

    for (int i = 0; i < NC; i++) {
        CPW1();
        __syncthreads();
        // issue stage i+2 (into slot (i+2)%3 = slot of finished chunk i-1)
        if (i + 2 < NC) {
            uint32_t st = ((i + 2) % NSTG) * STG;
            int k0 = (i + 2) * 32;
            CPA(d0 + st,             a0 + k0);  CPA(d0 + st + 16,         a0 + k0 + 8);
            if (G1) { CPA(d0 + st + 10240, a1 + k0); CPA(d0 + st + 10240 + 16, a1 + k0 + 8); }
            CPA(d0 + st + (G1 ? 20480 : 10240),      b0 + k0);
            CPA(d0 + st + (G1 ? 20480 : 10240) + 16, b0 + k0 + 8);
            if (!G1) { CPA(d0 + st + 20480, b1 + k0); CPA(d0 + st + 20480 + 16, b1 + k0 + 8); }
        }
        CPC();

        uint32_t st = (i % NSTG) * STG;
        #pragma unroll
        for (int kk = 0; kk < 2; kk++) {
            uint32_t af[2][4], as[2][4];
            ldsm4(af[0], aOff + st + kk * 32);
            ldsm4(af[1], aOff + st + kk * 32 + 1280);
            if (G1) {
                ldsm4(as[0], aOff + st + kk * 32 + 10240);
                ldsm4(as[1], aOff + st + kk * 32 + 10240 + 1280);
            }
            #pragma unroll
            for (int ng = 0; ng < 4; ng++) {
                uint32_t bf[4], bs[4];
                ldsm4(bf, bOff + st + ng * 1280 + kk * 32);
                if (!G1) ldsm4(bs, bOff + st + ng * 1280 + kk * 32 + 10240);
                #pragma unroll
                for (int mi = 0; mi < 2; mi++) {
                    if (G1) {
                        mma16816(c[mi][2 * ng],     af[mi], bf);
                        mma16816(c[mi][2 * ng],     as[mi], bf);
                        mma16816(c[mi][2 * ng + 1], af[mi], bf + 2);
                        mma16816(c[mi][2 * ng + 1], as[mi], bf + 2);
                    } else {
                        mma16816(c[mi][2 * ng],     af[mi], bf);
                        mma16816(c[mi][2 * ng],     af[mi], bs);
                        mma16816(c[mi][2 * ng + 1], af[mi], bf + 2);
                        mma16816(c[mi][2 * ng + 1], af[mi], bs + 2);
                    }
                }
            }
        }
    }

    // ---- epilogue: stage C in smem (pitch 132 floats), then coalesced out ----
    __syncthreads();
    float* sC = (float*)dsm;
    #pragma unroll
    for (int mi = 0; mi < 2; mi++) {
        #pragma unroll
        for (int nf = 0; nf < 8; nf++) {
            int rm = wm * 32 + mi * 16 + (lane >> 2);
            int cn = wn * 64 + nf * 8 + 2 * (lane & 3);
            *(float2*)&sC[rm * 132 + cn]       = make_float2(c[mi][nf][0], c[mi][nf][1]);
            *(float2*)&sC[(rm + 8) * 132 + cn] = make_float2(c[mi][nf][2], c[mi][nf][3]);
        }
    }
    __syncthreads();

    int rr = tid >> 1;
    int cb = (tid & 1) * 64;
    bool mv = (m0 + rr) < cnt;
    if (G1) {
        if (mv) {
            size_t rowb = (size_t)(off + m0 + rr) * HDIM + n0 + cb;
            #pragma unroll
            for (int g = 0; g < 8; g++) {
                uint32_t H[4];
                #pragma unroll
                for (int p = 0; p < 4; p++) {
                    int col = cb + g * 8 + 2 * p;
                    float v0 = fmaxf(sC[rr * 132 + col]     + s_bias[col],     0.f);
                    float v1 = fmaxf(sC[rr * 132 + col + 1] + s_bias[col + 1], 0.f);
                    H[p] = hpack2(__float2half_rn(v0), __float2half_rn(v1));
                }
                *(uint4*)(g_h + rowb + g * 8) = *(uint4*)H;
            }
        }
    } else {
        if (mv) {
            int enc  = s_tok[rr];
            int tok  = enc >> 1, slot = enc & 1;
            float gt = s_gate[rr];
            float* dst = g_y + ((size_t)slot * TOKENS + tok) * DDIM + n0 + cb;
            #pragma unroll
            for (int g = 0; g < 16; g++) {
                int col = cb + g * 4;
                float4 o;
                o.x = gt * (sC[rr * 132 + col]     + s_bias[col]);
                o.y = gt * (sC[rr * 132 + col + 1] + s_bias[col + 1]);
                o.z = gt * (sC[rr * 132 + col + 2] + s_bias[col + 2]);
                o.w = gt * (sC[rr * 132 + col + 3] + s_bias[col + 3]);
                *(float4*)(dst + g * 4) = o;
            }
        }
    }
}

__global__ void combine_kernel(float* __restrict__ out) {
    size_t i = ((size_t)blockIdx.x * 256 + threadIdx.x) * 4;
    float4 a = *(const float4*)(g_y + i);
    float4 b = *(const float4*)(g_y + (size_t)TOKENS * DDIM + i);
    float4 o;
    o.x = a.x + b.x; o.y = a.y + b.y; o.z = a.z + b.z; o.w = a.w + b.w;
    *(float4*)(out + i) = o;
}

// ---------------- launch ------------------------------------------------------
extern "C" void kernel_launch(void* const* d_in, const int* in_sizes, int n_in,
                              void* d_out, int out_size) {
    const float* x   = (const float*)d_in[0];
    const float* rw  = (const float*)d_in[1];
    const float* rb  = (const float*)d_in[2];
    const float* w1  = (const float*)d_in[3];
    const float* b1  = (const float*)d_in[4];
    const float* w2  = (const float*)d_in[5];
    const float* b2  = (const float*)d_in[6];
    float*       out = (float*)d_out;

    cudaFuncSetAttribute(hgemm_kernel<true>,
                         cudaFuncAttributeMaxDynamicSharedMemorySize, DSMEM);
    cudaFuncSetAttribute(hgemm_kernel<false>,
                         cudaFuncAttributeMaxDynamicSharedMemorySize, DSMEM);

    zero_counts_kernel<<<1, 32>>>();
    router_kernel<<<TOKENS / 8, 256>>>(x, rw, rb);
    offsets_kernel<<<1, 32>>>();

    split_x_kernel<<<TOKENS * DDIM / 1024, 256>>>(x);
    t_w1_kernel<<<dim3(HDIM / 32, DDIM / 32, NEXP), dim3(32, 8)>>>(w1);
    t_w2_kernel<<<dim3(DDIM / 32, HDIM / 32, NEXP), dim3(32, 8)>>>(w2);

    hgemm_kernel<true ><<<dim3(HDIM / 128, CAP / 128, NEXP), 256, DSMEM>>>(b1);
    hgemm_kernel<false><<<dim3(DDIM / 128, CAP / 128, NEXP), 256, DSMEM>>>(b2);

    combine_kernel<<<TOKENS * DDIM / 1024, 256>>>(out);
}

// round 6
// speedup vs baseline: 4.7844x; 1.5716x over previous
#include <cuda_runtime.h>
#include <cuda_fp16.h>
#include <math.h>
#include <stdint.h>

#define TOKENS 65536
#define DDIM   512
#define NEXP   8
#define HDIM   2048
#define CAP    65536

// ---------------- device scratch (no allocs allowed) -------------------------
__device__ int   g_counts [NEXP];
__device__ int   g_offsets[NEXP];
__device__ int   g_tokens [NEXP * CAP];   // token*2 + slot
__device__ float g_gates  [NEXP * CAP];
__device__ __half g_xh [(size_t)TOKENS * DDIM];          // x fp16
__device__ __half g_w1t[(size_t)NEXP * HDIM * DDIM];     // [E][H][D] K-major
__device__ __half g_w2t[(size_t)NEXP * DDIM * HDIM];     // [E][D][H] K-major
__device__ __half g_h[(size_t)2 * TOKENS * HDIM];        // compact hidden fp16
__device__ float g_y[(size_t)2 * TOKENS * DDIM];         // slot outputs

// ---------------- helpers -----------------------------------------------------
__device__ __forceinline__ uint32_t smem_u32(const void* p) {
    uint32_t a;
    asm("{ .reg .u64 t; cvta.to.shared.u64 t, %1; cvt.u32.u64 %0, t; }" : "=r"(a) : "l"(p));
    return a;
}
__device__ __forceinline__ void ldsm4(uint32_t* r, uint32_t addr) {
    asm volatile("ldmatrix.sync.aligned.m8n8.x4.shared.b16 {%0,%1,%2,%3}, [%4];"
        : "=r"(r[0]), "=r"(r[1]), "=r"(r[2]), "=r"(r[3]) : "r"(addr));
}
__device__ __forceinline__ void mma16816(float* c, const uint32_t* a, const uint32_t* b) {
    asm volatile(
        "mma.sync.aligned.m16n8k16.row.col.f32.f16.f16.f32 "
        "{%0,%1,%2,%3}, {%4,%5,%6,%7}, {%8,%9}, {%0,%1,%2,%3};"
        : "+f"(c[0]), "+f"(c[1]), "+f"(c[2]), "+f"(c[3])
        : "r"(a[0]), "r"(a[1]), "r"(a[2]), "r"(a[3]), "r"(b[0]), "r"(b[1]));
}
#define CPA(dst, src) \
    asm volatile("cp.async.cg.shared.global [%0], [%1], 16;" :: "r"(dst), "l"(src) : "memory")
#define CPC()  asm volatile("cp.async.commit_group;" ::: "memory")
#define CPW2() asm volatile("cp.async.wait_group 2;" ::: "memory")

__device__ __forceinline__ uint32_t hpack2(__half a, __half b) {
    union { __half h[2]; uint32_t u; } t;
    t.h[0] = a; t.h[1] = b;
    return t.u;
}

// ---------------- prep kernels ------------------------------------------------
__global__ void zero_counts_kernel() { if (threadIdx.x < NEXP) g_counts[threadIdx.x] = 0; }

__global__ void offsets_kernel() {
    if (threadIdx.x == 0) {
        int s = 0;
        #pragma unroll
        for (int e = 0; e < NEXP; e++) { g_offsets[e] = s; s += g_counts[e]; }
    }
}

__global__ void conv_x_kernel(const float* __restrict__ x) {
    size_t i = ((size_t)blockIdx.x * 256 + threadIdx.x) * 4;
    float4 v = *(const float4*)(x + i);
    uint2 H;
    H.x = hpack2(__float2half_rn(v.x), __float2half_rn(v.y));
    H.y = hpack2(__float2half_rn(v.z), __float2half_rn(v.w));
    *(uint2*)(g_xh + i) = H;
}

// transpose [R][C] fp32 -> [C][R] fp16 (per expert)
template<int SEL>   // 0: w1 (R=512,C=2048), 1: w2 (R=2048,C=512)
__global__ void t_w_kernel(const float* __restrict__ src) {
    constexpr int R = SEL ? HDIM : DDIM;
    constexpr int C = SEL ? DDIM : HDIM;
    __half* dst = SEL ? g_w2t : g_w1t;
    __shared__ float t[32][33];
    int e = blockIdx.z;
    const float* s = src + (size_t)e * R * C;
    int c0 = blockIdx.x * 32, r0 = blockIdx.y * 32;
    int tx = threadIdx.x, ty = threadIdx.y;
    #pragma unroll
    for (int j = 0; j < 4; j++)
        t[ty + j * 8][tx] = s[(size_t)(r0 + ty + j * 8) * C + c0 + tx];
    __syncthreads();
    #pragma unroll
    for (int j = 0; j < 4; j++) {
        float v = t[tx][ty + j * 8];
        size_t o = ((size_t)e * C + c0 + ty + j * 8) * R + r0 + tx;
        dst[o] = __float2half_rn(v);
    }
}

// ---------------- router ------------------------------------------------------
__global__ void router_kernel(const float* __restrict__ x,
                              const float* __restrict__ rw,
                              const float* __restrict__ rb) {
    __shared__ float srw[DDIM * NEXP];
    int tid = threadIdx.x;
    for (int i = tid; i < DDIM * NEXP; i += blockDim.x) srw[i] = rw[i];
    __syncthreads();
    int warp = tid >> 5, lane = tid & 31;
    int t = blockIdx.x * 8 + warp;
    const float* xr = x + (size_t)t * DDIM;
    float acc[NEXP];
    #pragma unroll
    for (int e = 0; e < NEXP; e++) acc[e] = 0.f;
    for (int d = lane; d < DDIM; d += 32) {
        float xv = xr[d];
        #pragma unroll
        for (int e = 0; e < NEXP; e++) acc[e] += xv * srw[d * NEXP + e];
    }
    #pragma unroll
    for (int e = 0; e < NEXP; e++) {
        #pragma unroll
        for (int o = 16; o > 0; o >>= 1)
            acc[e] += __shfl_xor_sync(0xffffffffu, acc[e], o);
    }
    if (lane == 0) {
        float l[NEXP];
        #pragma unroll
        for (int e = 0; e < NEXP; e++) l[e] = acc[e] + rb[e];
        int e1 = 0;
        #pragma unroll
        for (int e = 1; e < NEXP; e++) if (l[e] > l[e1]) e1 = e;
        int e2 = (e1 == 0) ? 1 : 0;
        #pragma unroll
        for (int e = 0; e < NEXP; e++)
            if (e != e1 && l[e] > l[e2]) e2 = e;
        float d2 = expf(l[e2] - l[e1]);
        float g2 = d2 / (1.f + d2);
        float g1 = 1.f - g2;
        int p1 = atomicAdd(&g_counts[e1], 1);
        g_tokens[e1 * CAP + p1] = t * 2 + 0;  g_gates[e1 * CAP + p1] = g1;
        int p2 = atomicAdd(&g_counts[e2], 1);
        g_tokens[e2 * CAP + p2] = t * 2 + 1;  g_gates[e2 * CAP + p2] = g2;
    }
}

// ---------------- HMMA GEMM ---------------------------------------------------
// Tile 128x128x32, single fp16, 4-stage cp.async pipeline (3 in flight).
// Stage: A @0 (128x80B=10240), B @10240. STG=20480.
#define STG   20480
#define NSTG  4
#define DSMEM (NSTG * STG)

template<bool G1>
__global__ void __launch_bounds__(256, 2)
hgemm_kernel(const float* __restrict__ bias_vec) {
    constexpr int KTOT = G1 ? DDIM : HDIM;
    constexpr int NTOT = G1 ? HDIM : DDIM;
    constexpr int NC   = KTOT / 32;

    int e   = blockIdx.z;
    int cnt = g_counts[e];
    int m0  = blockIdx.y * 128;
    if (m0 >= cnt) return;
    int n0  = blockIdx.x * 128;
    int off = g_offsets[e];

    extern __shared__ char dsm[];
    __shared__ int   s_tok[128];
    __shared__ float s_gate[128];
    __shared__ float s_bias[128];

    int tid = threadIdx.x;
    int lane = tid & 31, wid = tid >> 5;

    if (tid < 128) {
        int m = m0 + tid; if (m > cnt - 1) m = cnt - 1;
        s_tok[tid]  = g_tokens[e * CAP + m];
        s_gate[tid] = g_gates [e * CAP + m];
        s_bias[tid] = bias_vec[(size_t)e * NTOT + n0 + tid];
    }
    __syncthreads();

    // ---- cp.async mapping: thread t -> row t/2, 32B half (t&1) of 64B row ----
    int r    = tid >> 1;
    int eoff = (tid & 1) * 16;
    size_t aRow;
    if (G1) aRow = (size_t)(s_tok[r] >> 1) * DDIM;
    else {
        int mm = m0 + r; if (mm > cnt - 1) mm = cnt - 1;
        aRow = (size_t)(off + mm) * HDIM;
    }
    const __half* aP = (G1 ? g_xh : g_h) + aRow + eoff;
    const __half* bP = (G1 ? g_w1t : g_w2t) +
                       ((size_t)e * NTOT + n0 + r) * KTOT + eoff;

    uint32_t sb = smem_u32(dsm);
    uint32_t dA = sb + 80 * r + 32 * (tid & 1);
    uint32_t dB = dA + 10240;

    // ---- ldmatrix base addresses ----
    int wm = wid & 3, wn = wid >> 2;       // warp tile: rows wm*32, cols wn*64
    uint32_t aOff = sb + 80 * (wm * 32 + (lane & 15)) + 16 * (lane >> 4);
    uint32_t bOff = sb + 10240 +
                    80 * (wn * 64 + (lane & 7) + 8 * (lane >> 4)) +
                    16 * ((lane >> 3) & 1);

    float c[2][8][4];
    #pragma unroll
    for (int i = 0; i < 2; i++)
        #pragma unroll
        for (int j = 0; j < 8; j++)
            #pragma unroll
            for (int q = 0; q < 4; q++) c[i][j][q] = 0.f;

    // ---- prologue: stages 0,1,2 ----
    #pragma unroll
    for (int i = 0; i < 3; i++) {
        uint32_t st = i * STG;
        int k0 = i * 32;
        CPA(dA + st, aP + k0);  CPA(dA + st + 16, aP + k0 + 8);
        CPA(dB + st, bP + k0);  CPA(dB + st + 16, bP + k0 + 8);
        CPC();
    }

    for (int i = 0; i < NC; i++) {
        CPW2();
        __syncthreads();
        if (i + 3 < NC) {
            uint32_t st = ((i + 3) % NSTG) * STG;
            int k0 = (i + 3) * 32;
            CPA(dA + st, aP + k0);  CPA(dA + st + 16, aP + k0 + 8);
            CPA(dB + st, bP + k0);  CPA(dB + st + 16, bP + k0 + 8);
        }
        CPC();

        uint32_t st = (i % NSTG) * STG;
        #pragma unroll
        for (int kk = 0; kk < 2; kk++) {
            uint32_t a0[4], a1[4];
            ldsm4(a0, aOff + st + kk * 32);
            ldsm4(a1, aOff + st + kk * 32 + 1280);
            #pragma unroll
            for (int ng = 0; ng < 4; ng++) {
                uint32_t bf[4];
                ldsm4(bf, bOff + st + ng * 1280 + kk * 32);
                mma16816(c[0][2 * ng],     a0, bf);
                mma16816(c[0][2 * ng + 1], a0, bf + 2);
                mma16816(c[1][2 * ng],     a1, bf);
                mma16816(c[1][2 * ng + 1], a1, bf + 2);
            }
        }
    }

    // ---- epilogue: stage C in smem (pitch 132 floats), then coalesced out ----
    __syncthreads();
    float* sC = (float*)dsm;
    #pragma unroll
    for (int mi = 0; mi < 2; mi++) {
        #pragma unroll
        for (int nf = 0; nf < 8; nf++) {
            int rm = wm * 32 + mi * 16 + (lane >> 2);
            int cn = wn * 64 + nf * 8 + 2 * (lane & 3);
            *(float2*)&sC[rm * 132 + cn]       = make_float2(c[mi][nf][0], c[mi][nf][1]);
            *(float2*)&sC[(rm + 8) * 132 + cn] = make_float2(c[mi][nf][2], c[mi][nf][3]);
        }
    }
    __syncthreads();

    int rr = tid >> 1;
    int cb = (tid & 1) * 64;
    bool mv = (m0 + rr) < cnt;
    if (G1) {
        if (mv) {
            size_t rowb = (size_t)(off + m0 + rr) * HDIM + n0 + cb;
            #pragma unroll
            for (int g = 0; g < 8; g++) {
                uint32_t H[4];
                #pragma unroll
                for (int p = 0; p < 4; p++) {
                    int col = cb + g * 8 + 2 * p;
                    float v0 = fmaxf(sC[rr * 132 + col]     + s_bias[col],     0.f);
                    float v1 = fmaxf(sC[rr * 132 + col + 1] + s_bias[col + 1], 0.f);
                    H[p] = hpack2(__float2half_rn(v0), __float2half_rn(v1));
                }
                *(uint4*)(g_h + rowb + g * 8) = *(uint4*)H;
            }
        }
    } else {
        if (mv) {
            int enc  = s_tok[rr];
            int tok  = enc >> 1, slot = enc & 1;
            float gt = s_gate[rr];
            float* dst = g_y + ((size_t)slot * TOKENS + tok) * DDIM + n0 + cb;
            #pragma unroll
            for (int g = 0; g < 16; g++) {
                int col = cb + g * 4;
                float4 o;
                o.x = gt * (sC[rr * 132 + col]     + s_bias[col]);
                o.y = gt * (sC[rr * 132 + col + 1] + s_bias[col + 1]);
                o.z = gt * (sC[rr * 132 + col + 2] + s_bias[col + 2]);
                o.w = gt * (sC[rr * 132 + col + 3] + s_bias[col + 3]);
                *(float4*)(dst + g * 4) = o;
            }
        }
    }
}

__global__ void combine_kernel(float* __restrict__ out) {
    size_t i = ((size_t)blockIdx.x * 256 + threadIdx.x) * 4;
    float4 a = *(const float4*)(g_y + i);
    float4 b = *(const float4*)(g_y + (size_t)TOKENS * DDIM + i);
    float4 o;
    o.x = a.x + b.x; o.y = a.y + b.y; o.z = a.z + b.z; o.w = a.w + b.w;
    *(float4*)(out + i) = o;
}

// ---------------- launch ------------------------------------------------------
extern "C" void kernel_launch(void* const* d_in, const int* in_sizes, int n_in,
                              void* d_out, int out_size) {
    const float* x   = (const float*)d_in[0];
    const float* rw  = (const float*)d_in[1];
    const float* rb  = (const float*)d_in[2];
    const float* w1  = (const float*)d_in[3];
    const float* b1  = (const float*)d_in[4];
    const float* w2  = (const float*)d_in[5];
    const float* b2  = (const float*)d_in[6];
    float*       out = (float*)d_out;

    cudaFuncSetAttribute(hgemm_kernel<true>,
                         cudaFuncAttributeMaxDynamicSharedMemorySize, DSMEM);
    cudaFuncSetAttribute(hgemm_kernel<false>,
                         cudaFuncAttributeMaxDynamicSharedMemorySize, DSMEM);

    zero_counts_kernel<<<1, 32>>>();
    router_kernel<<<TOKENS / 8, 256>>>(x, rw, rb);
    offsets_kernel<<<1, 32>>>();

    conv_x_kernel<<<TOKENS * DDIM / 1024, 256>>>(x);
    t_w_kernel<0><<<dim3(HDIM / 32, DDIM / 32, NEXP), dim3(32, 8)>>>(w1);
    t_w_kernel<1><<<dim3(DDIM / 32, HDIM / 32, NEXP), dim3(32, 8)>>>(w2);

    hgemm_kernel<true ><<<dim3(HDIM / 128, CAP / 128, NEXP), 256, DSMEM>>>(b1);
    hgemm_kernel<false><<<dim3(DDIM / 128, CAP / 128, NEXP), 256, DSMEM>>>(b2);

    combine_kernel<<<TOKENS * DDIM / 1024, 256>>>(out);
}